// round 7
// baseline (speedup 1.0000x reference)
#include <cuda_runtime.h>
#include <cuda_bf16.h>
#include <math.h>

#define NGP_L 16
#define NGP_T (1 << 19)
#define N_PTS (64 * 64 * 64)
#define BLOCK 256

struct LevelParams {
    int res[NGP_L];
    unsigned dense_mask;
};

__global__ __launch_bounds__(BLOCK, 5)
void hashgrid_mlp_kernel(const float* __restrict__ points,
                         const float* __restrict__ table,
                         const float* __restrict__ w1,
                         const float* __restrict__ w2,
                         float* __restrict__ out,
                         LevelParams lp)
{
    __shared__ float sw1[64 * 32];
    __shared__ float sw2[64];
    __shared__ __nv_bfloat162 senc[NGP_L * BLOCK];  // per-level features, packed

    const int tid = threadIdx.x;
    for (int i = tid; i < 64 * 32; i += BLOCK) sw1[i] = w1[i];
    if (tid < 64) sw2[tid] = w2[tid];
    __syncthreads();

    const int p = blockIdx.x * BLOCK + tid;   // N_PTS % BLOCK == 0

    const float px = points[3 * p + 0];
    const float py = points[3 * p + 1];
    const float pz = points[3 * p + 2];

    const unsigned M = (unsigned)(NGP_T - 1);

#pragma unroll
    for (int l = 0; l < NGP_L; l++) {
        const int   res   = lp.res[l];
        const float rf    = (float)res;
        const bool  dense = (lp.dense_mask >> l) & 1u;
        const unsigned r1 = (unsigned)(res + 1);

        const float x = px * rf, y = py * rf, z = pz * rf;
        const float x0 = floorf(x), y0 = floorf(y), z0 = floorf(z);
        const float fx = x - x0, fy = y - y0, fz = z - z0;
        const unsigned cx0 = (unsigned)x0, cy0 = (unsigned)y0, cz0 = (unsigned)z0;

        const float2* __restrict__ tab = (const float2*)table + (size_t)l * NGP_T;

        // x-paired corners: one aligned float4 covers both corners whenever
        // idx0^idx1==1 (~50% of lanes), else a predicated fallback float2.
        unsigned idx0[4], idx1[4];
        if (dense) {
            const unsigned b  = cx0 + r1 * (cy0 + r1 * cz0);
            const unsigned dy = r1;
            const unsigned dz = r1 * r1;
            idx0[0] = b;           idx0[1] = b + dz;
            idx0[2] = b + dy;      idx0[3] = b + dy + dz;
#pragma unroll
            for (int q = 0; q < 4; q++) idx1[q] = idx0[q] + 1;
        } else {
            const unsigned ha = cy0 * 2654435761u, hb = ha + 2654435761u;
            const unsigned hc = cz0 * 805459861u,  hd = hc + 805459861u;
            unsigned h[4] = { ha ^ hc, ha ^ hd, hb ^ hc, hb ^ hd };
#pragma unroll
            for (int q = 0; q < 4; q++) {
                idx0[q] = (cx0 ^ h[q]) & M;
                idx1[q] = ((cx0 + 1u) ^ h[q]) & M;
            }
        }

        // Issue all 4 wide loads first (max MLP)
        float4 v[4];
#pragma unroll
        for (int q = 0; q < 4; q++)
            v[q] = __ldg((const float4*)(tab + (idx0[q] & ~1u)));

        float2 c0[4], c1[4];
#pragma unroll
        for (int q = 0; q < 4; q++) {
            const bool odd0 = (idx0[q] & 1u);
            c0[q] = odd0 ? make_float2(v[q].z, v[q].w) : make_float2(v[q].x, v[q].y);
            c1[q] = odd0 ? make_float2(v[q].x, v[q].y) : make_float2(v[q].z, v[q].w);
            if ((idx0[q] ^ idx1[q]) != 1u)
                c1[q] = __ldg(tab + idx1[q]);
        }

        const float wy0 = 1.0f - fy, wz0 = 1.0f - fz;
        const float wq[4] = { wy0 * wz0, wy0 * fz, fy * wz0, fy * fz };

        float e0 = 0.0f, e1 = 0.0f;
#pragma unroll
        for (int q = 0; q < 4; q++) {
            const float gx = fmaf(fx, c1[q].x - c0[q].x, c0[q].x);
            const float gy = fmaf(fx, c1[q].y - c0[q].y, c0[q].y);
            e0 = fmaf(wq[q], gx, e0);
            e1 = fmaf(wq[q], gy, e1);
        }

        // Retire this level's features to shared immediately (frees registers).
        senc[l * BLOCK + tid] = __floats2bfloat162_rn(e0, e1);
    }

    // Reload encoding into registers for the MLP tail.
    float enc[32];
#pragma unroll
    for (int l = 0; l < NGP_L; l++) {
        const float2 e = __bfloat1622float2(senc[l * BLOCK + tid]);
        enc[2 * l + 0] = e.x;
        enc[2 * l + 1] = e.y;
    }

    // Fused MLP: h = relu(enc @ w1^T) [64], out = sigmoid(h @ w2^T)
    float acc = 0.0f;
#pragma unroll 4
    for (int j = 0; j < 64; j++) {
        float h = 0.0f;
        const float* wr = &sw1[j * 32];
#pragma unroll
        for (int k = 0; k < 32; k++) h = fmaf(enc[k], wr[k], h);
        acc = fmaf(sw2[j], fmaxf(h, 0.0f), acc);
    }

    out[p] = 1.0f / (1.0f + __expf(-acc));
}

extern "C" void kernel_launch(void* const* d_in, const int* in_sizes, int n_in,
                              void* d_out, int out_size)
{
    const float* points = (const float*)d_in[0];   // [N_PTS, 3]
    const float* table  = (const float*)d_in[1];   // [L, T, 2]
    const float* w1     = (const float*)d_in[2];   // [64, 32]
    const float* w2     = (const float*)d_in[3];   // [1, 64]
    float* out = (float*)d_out;                    // [N_PTS]

    LevelParams lp;
    unsigned mask = 0;
    for (int l = 0; l < NGP_L; l++) {
        double r = floor(16.0 * pow(1.447269237440378, (double)l) + 1e-6);
        int res = (int)r;
        lp.res[l] = res;
        long long r1 = (long long)res + 1;
        if (r1 * r1 * r1 <= (long long)NGP_T) mask |= (1u << l);
    }
    lp.dense_mask = mask;

    hashgrid_mlp_kernel<<<N_PTS / BLOCK, BLOCK>>>(points, table, w1, w2, out, lp);
}

// round 8
// speedup vs baseline: 1.2748x; 1.2748x over previous
#include <cuda_runtime.h>
#include <math.h>

#define NGP_L 16
#define NGP_T (1 << 19)
#define N_PTS (64 * 64 * 64)
#define BLOCK 256

struct LevelParams {
    int res[NGP_L];
    unsigned dense_mask;
};

__global__ __launch_bounds__(BLOCK, 4)
void hashgrid_mlp_kernel(const float* __restrict__ points,
                         const float* __restrict__ table,
                         const float* __restrict__ w1,
                         const float* __restrict__ w2,
                         float* __restrict__ out,
                         LevelParams lp)
{
    __shared__ float sw1[64 * 32];
    __shared__ float sw2[64];

    const int tid = threadIdx.x;
    for (int i = tid; i < 64 * 32; i += BLOCK) sw1[i] = w1[i];
    if (tid < 64) sw2[tid] = w2[tid];
    __syncthreads();

    const int p = blockIdx.x * BLOCK + tid;   // N_PTS % BLOCK == 0

    const float px = points[3 * p + 0];
    const float py = points[3 * p + 1];
    const float pz = points[3 * p + 2];

    const unsigned M = (unsigned)(NGP_T - 1);

    float enc[2 * NGP_L];

#pragma unroll
    for (int l = 0; l < NGP_L; l++) {
        const int   res   = lp.res[l];
        const float rf    = (float)res;
        const bool  dense = (lp.dense_mask >> l) & 1u;
        const unsigned r1 = (unsigned)(res + 1);

        const float x = px * rf, y = py * rf, z = pz * rf;
        const float x0 = floorf(x), y0 = floorf(y), z0 = floorf(z);
        const float fx = x - x0, fy = y - y0, fz = z - z0;
        const unsigned cx0 = (unsigned)x0, cy0 = (unsigned)y0, cz0 = (unsigned)z0;

        const float2* __restrict__ tab = (const float2*)table + (size_t)l * NGP_T;

        // Pair corners along x: idx0 = corner(ox=0), idx1 = corner(ox=1) for
        // each of 4 (oy,oz) combos. One aligned float4 covers both whenever
        // idx0^idx1==1 (~50% of lanes), else predicated fallback float2 load.
        unsigned idx0[4], idx1[4];
        if (dense) {
            const unsigned b  = cx0 + r1 * (cy0 + r1 * cz0);
            const unsigned dy = r1;
            const unsigned dz = r1 * r1;
            idx0[0] = b;           idx0[1] = b + dz;
            idx0[2] = b + dy;      idx0[3] = b + dy + dz;
#pragma unroll
            for (int q = 0; q < 4; q++) idx1[q] = idx0[q] + 1;
        } else {
            const unsigned ha = cy0 * 2654435761u, hb = ha + 2654435761u;
            const unsigned hc = cz0 * 805459861u,  hd = hc + 805459861u;
            unsigned h[4] = { ha ^ hc, ha ^ hd, hb ^ hc, hb ^ hd };
#pragma unroll
            for (int q = 0; q < 4; q++) {
                idx0[q] = (cx0 ^ h[q]) & M;
                idx1[q] = ((cx0 + 1u) ^ h[q]) & M;
            }
        }

        // Issue all 4 wide loads first (max MLP)
        float4 v[4];
#pragma unroll
        for (int q = 0; q < 4; q++)
            v[q] = __ldg((const float4*)(tab + (idx0[q] & ~1u)));

        // corner0 from v; corner1 from opposite half when adjacent, else fallback
        float2 c0[4], c1[4];
#pragma unroll
        for (int q = 0; q < 4; q++) {
            const bool odd0 = (idx0[q] & 1u);
            c0[q] = odd0 ? make_float2(v[q].z, v[q].w) : make_float2(v[q].x, v[q].y);
            c1[q] = odd0 ? make_float2(v[q].x, v[q].y) : make_float2(v[q].z, v[q].w);
            if ((idx0[q] ^ idx1[q]) != 1u)
                c1[q] = __ldg(tab + idx1[q]);
        }

        // Trilinear blend: lerp in x, then weight by (oy,oz) products
        const float wy0 = 1.0f - fy, wz0 = 1.0f - fz;
        const float wq[4] = { wy0 * wz0, wy0 * fz, fy * wz0, fy * fz };

        float e0 = 0.0f, e1 = 0.0f;
#pragma unroll
        for (int q = 0; q < 4; q++) {
            const float gx = fmaf(fx, c1[q].x - c0[q].x, c0[q].x);
            const float gy = fmaf(fx, c1[q].y - c0[q].y, c0[q].y);
            e0 = fmaf(wq[q], gx, e0);
            e1 = fmaf(wq[q], gy, e1);
        }
        enc[2 * l + 0] = e0;
        enc[2 * l + 1] = e1;
    }

    // Fused MLP: h = relu(enc @ w1^T) [64], out = sigmoid(h @ w2^T)
    // Weight reads vectorized: LDS.128 broadcast (512 loads vs 2048 scalar),
    // cutting shared-load traffic on the L1tex/LSU path by 4x.
    float acc = 0.0f;
#pragma unroll 4
    for (int j = 0; j < 64; j++) {
        const float4* __restrict__ wr = (const float4*)&sw1[j * 32];
        float h = 0.0f;
#pragma unroll
        for (int k = 0; k < 8; k++) {
            const float4 w = wr[k];
            h = fmaf(enc[4 * k + 0], w.x, h);
            h = fmaf(enc[4 * k + 1], w.y, h);
            h = fmaf(enc[4 * k + 2], w.z, h);
            h = fmaf(enc[4 * k + 3], w.w, h);
        }
        acc = fmaf(sw2[j], fmaxf(h, 0.0f), acc);
    }

    out[p] = 1.0f / (1.0f + __expf(-acc));
}

extern "C" void kernel_launch(void* const* d_in, const int* in_sizes, int n_in,
                              void* d_out, int out_size)
{
    const float* points = (const float*)d_in[0];   // [N_PTS, 3]
    const float* table  = (const float*)d_in[1];   // [L, T, 2]
    const float* w1     = (const float*)d_in[2];   // [64, 32]
    const float* w2     = (const float*)d_in[3];   // [1, 64]
    float* out = (float*)d_out;                    // [N_PTS]

    LevelParams lp;
    unsigned mask = 0;
    for (int l = 0; l < NGP_L; l++) {
        double r = floor(16.0 * pow(1.447269237440378, (double)l) + 1e-6);
        int res = (int)r;
        lp.res[l] = res;
        long long r1 = (long long)res + 1;
        if (r1 * r1 * r1 <= (long long)NGP_T) mask |= (1u << l);
    }
    lp.dense_mask = mask;

    hashgrid_mlp_kernel<<<N_PTS / BLOCK, BLOCK>>>(points, table, w1, w2, out, lp);
}

// round 11
// speedup vs baseline: 1.4679x; 1.1515x over previous
#include <cuda_runtime.h>
#include <cuda_bf16.h>
#include <math.h>

#define NGP_L 16
#define NGP_T (1 << 19)
#define N_PTS (64 * 64 * 64)
#define BLOCK 256

struct LevelParams {
    int res[NGP_L];
    unsigned dense_mask;
};

__global__ __launch_bounds__(BLOCK, 4)
void hashgrid_mlp_kernel(const float* __restrict__ points,
                         const float* __restrict__ table,
                         const float* __restrict__ w1,
                         const float* __restrict__ w2,
                         float* __restrict__ out,
                         LevelParams lp)
{
    // w1 packed as bf16x2 pairs: sw1[j*16 + kk] = (w1[j][2kk], w1[j][2kk+1])
    __shared__ __align__(16) __nv_bfloat162 sw1[64 * 16];
    __shared__ float sw2[64];

    const int tid = threadIdx.x;
    for (int i = tid; i < 64 * 16; i += BLOCK)
        sw1[i] = __floats2bfloat162_rn(w1[2 * i], w1[2 * i + 1]);
    if (tid < 64) sw2[tid] = w2[tid];
    __syncthreads();

    const int p = blockIdx.x * BLOCK + tid;   // N_PTS % BLOCK == 0

    const float px = points[3 * p + 0];
    const float py = points[3 * p + 1];
    const float pz = points[3 * p + 2];

    const unsigned M = (unsigned)(NGP_T - 1);

    // Encoding kept as 16 packed bf16x2 registers (frees 16 regs vs fp32,
    // giving ptxas slack to pipeline loads across levels).
    __nv_bfloat162 encp[NGP_L];

#pragma unroll
    for (int l = 0; l < NGP_L; l++) {
        const int   res   = lp.res[l];
        const float rf    = (float)res;
        const bool  dense = (lp.dense_mask >> l) & 1u;
        const unsigned r1 = (unsigned)(res + 1);

        const float x = px * rf, y = py * rf, z = pz * rf;
        const float x0 = floorf(x), y0 = floorf(y), z0 = floorf(z);
        const float fx = x - x0, fy = y - y0, fz = z - z0;
        const unsigned cx0 = (unsigned)x0, cy0 = (unsigned)y0, cz0 = (unsigned)z0;

        const float2* __restrict__ tab = (const float2*)table + (size_t)l * NGP_T;

        // x-paired corners: one aligned float4 covers both corners whenever
        // idx0^idx1==1 (~50% of lanes), else a predicated fallback float2.
        unsigned idx0[4], idx1[4];
        if (dense) {
            const unsigned b  = cx0 + r1 * (cy0 + r1 * cz0);
            const unsigned dy = r1;
            const unsigned dz = r1 * r1;
            idx0[0] = b;           idx0[1] = b + dz;
            idx0[2] = b + dy;      idx0[3] = b + dy + dz;
#pragma unroll
            for (int q = 0; q < 4; q++) idx1[q] = idx0[q] + 1;
        } else {
            const unsigned ha = cy0 * 2654435761u, hb = ha + 2654435761u;
            const unsigned hc = cz0 * 805459861u,  hd = hc + 805459861u;
            unsigned h[4] = { ha ^ hc, ha ^ hd, hb ^ hc, hb ^ hd };
#pragma unroll
            for (int q = 0; q < 4; q++) {
                idx0[q] = (cx0 ^ h[q]) & M;
                idx1[q] = ((cx0 + 1u) ^ h[q]) & M;
            }
        }

        // Issue all 4 wide loads first (max MLP)
        float4 v[4];
#pragma unroll
        for (int q = 0; q < 4; q++)
            v[q] = __ldg((const float4*)(tab + (idx0[q] & ~1u)));

        float2 c0[4], c1[4];
#pragma unroll
        for (int q = 0; q < 4; q++) {
            const bool odd0 = (idx0[q] & 1u);
            c0[q] = odd0 ? make_float2(v[q].z, v[q].w) : make_float2(v[q].x, v[q].y);
            c1[q] = odd0 ? make_float2(v[q].x, v[q].y) : make_float2(v[q].z, v[q].w);
            if ((idx0[q] ^ idx1[q]) != 1u)
                c1[q] = __ldg(tab + idx1[q]);
        }

        const float wy0 = 1.0f - fy, wz0 = 1.0f - fz;
        const float wq[4] = { wy0 * wz0, wy0 * fz, fy * wz0, fy * fz };

        float e0 = 0.0f, e1 = 0.0f;
#pragma unroll
        for (int q = 0; q < 4; q++) {
            const float gx = fmaf(fx, c1[q].x - c0[q].x, c0[q].x);
            const float gy = fmaf(fx, c1[q].y - c0[q].y, c0[q].y);
            e0 = fmaf(wq[q], gx, e0);
            e1 = fmaf(wq[q], gy, e1);
        }
        encp[l] = __floats2bfloat162_rn(e0, e1);   // features (2l, 2l+1) packed
    }

    // Fused MLP in bf16x2 SIMD: h_j = sum_kk dot(encp[kk], w1p[j][kk])
    // 16 HFMA2 per hidden unit (vs 32 FFMA), weights via LDS.128.
    float acc = 0.0f;
#pragma unroll 4
    for (int j = 0; j < 64; j++) {
        const uint4* __restrict__ wv = (const uint4*)&sw1[j * 16];
        __nv_bfloat162 hh = __floats2bfloat162_rn(0.0f, 0.0f);
#pragma unroll
        for (int q = 0; q < 4; q++) {
            const uint4 w = wv[q];
            hh = __hfma2(encp[4 * q + 0], reinterpret_cast<const __nv_bfloat162&>(w.x), hh);
            hh = __hfma2(encp[4 * q + 1], reinterpret_cast<const __nv_bfloat162&>(w.y), hh);
            hh = __hfma2(encp[4 * q + 2], reinterpret_cast<const __nv_bfloat162&>(w.z), hh);
            hh = __hfma2(encp[4 * q + 3], reinterpret_cast<const __nv_bfloat162&>(w.w), hh);
        }
        const float h = __low2float(hh) + __high2float(hh);
        acc = fmaf(sw2[j], fmaxf(h, 0.0f), acc);
    }

    out[p] = 1.0f / (1.0f + __expf(-acc));
}

extern "C" void kernel_launch(void* const* d_in, const int* in_sizes, int n_in,
                              void* d_out, int out_size)
{
    const float* points = (const float*)d_in[0];   // [N_PTS, 3]
    const float* table  = (const float*)d_in[1];   // [L, T, 2]
    const float* w1     = (const float*)d_in[2];   // [64, 32]
    const float* w2     = (const float*)d_in[3];   // [1, 64]
    float* out = (float*)d_out;                    // [N_PTS]

    LevelParams lp;
    unsigned mask = 0;
    for (int l = 0; l < NGP_L; l++) {
        double r = floor(16.0 * pow(1.447269237440378, (double)l) + 1e-6);
        int res = (int)r;
        lp.res[l] = res;
        long long r1 = (long long)res + 1;
        if (r1 * r1 * r1 <= (long long)NGP_T) mask |= (1u << l);
    }
    lp.dense_mask = mask;

    hashgrid_mlp_kernel<<<N_PTS / BLOCK, BLOCK>>>(points, table, w1, w2, out, lp);
}